// round 1
// baseline (speedup 1.0000x reference)
#include <cuda_runtime.h>
#include <math.h>

#define BQ   8
#define NPIX 1024
#define CD   512
#define NH   8
#define HD   64

// Scratch (device globals: allocation-free rule)
__device__ float g_qkv[BQ * NPIX * 3 * CD];   // [8192][1536]
__device__ float g_attn[BQ * NPIX * CD];      // [8192][512]
__device__ float g_four[BQ * NPIX * CD];      // [8192][512]

// ---------------- f32x2 helpers (full-rate packed FMA on sm_103a) ----------
__device__ __forceinline__ unsigned long long f2dup(float a) {
    unsigned long long r;
    asm("mov.b64 %0, {%1, %1};" : "=l"(r) : "f"(a));
    return r;
}
__device__ __forceinline__ unsigned long long fma2(unsigned long long a,
                                                   unsigned long long b,
                                                   unsigned long long c) {
    unsigned long long d;
    asm("fma.rn.f32x2 %0, %1, %2, %3;" : "=l"(d) : "l"(a), "l"(b), "l"(c));
    return d;
}
__device__ __forceinline__ void unpk(unsigned long long v, float& lo, float& hi) {
    asm("mov.b64 {%0, %1}, %2;" : "=f"(lo), "=f"(hi) : "l"(v));
}

// ---------------- GEMM: C[M,N] = A[M,K] @ B[N,K]^T (both K-contiguous) -----
// 128x128 tile, BK=16, 256 threads, 8x8 per thread, f32x2 accumulators
// packed over M-pairs.
template <bool FUSE>
__global__ __launch_bounds__(256, 2)
void gemm_kernel(const float* __restrict__ A, const float* __restrict__ Bw,
                 float* __restrict__ Cout, int K, int N,
                 const float* __restrict__ bias,
                 const float* __restrict__ four,
                 const float* __restrict__ mixw) {
    const int LDT = 132;
    __shared__ float As[16 * LDT];
    __shared__ float Bs[16 * LDT];

    const int tid = threadIdx.x;
    const int tx = tid & 15;
    const int ty = tid >> 4;
    const int m0 = blockIdx.y * 128;
    const int n0 = blockIdx.x * 128;

    unsigned long long acc[4][8];
#pragma unroll
    for (int i = 0; i < 4; i++)
#pragma unroll
        for (int j = 0; j < 8; j++) acc[i][j] = 0ull;

    for (int kt = 0; kt < K; kt += 16) {
#pragma unroll
        for (int h = 0; h < 2; h++) {
            int v = tid + h * 256;           // 0..511
            int row = v >> 2;                // 0..127
            int kq = (v & 3) << 2;           // 0,4,8,12
            float4 ta = *(const float4*)(A + (size_t)(m0 + row) * K + kt + kq);
            As[(kq + 0) * LDT + row] = ta.x;
            As[(kq + 1) * LDT + row] = ta.y;
            As[(kq + 2) * LDT + row] = ta.z;
            As[(kq + 3) * LDT + row] = ta.w;
            float4 tb = *(const float4*)(Bw + (size_t)(n0 + row) * K + kt + kq);
            Bs[(kq + 0) * LDT + row] = tb.x;
            Bs[(kq + 1) * LDT + row] = tb.y;
            Bs[(kq + 2) * LDT + row] = tb.z;
            Bs[(kq + 3) * LDT + row] = tb.w;
        }
        __syncthreads();

#pragma unroll
        for (int kk = 0; kk < 16; kk++) {
            const float* ap = &As[kk * LDT + ty * 8];
            ulonglong2 a01 = *(const ulonglong2*)ap;
            ulonglong2 a23 = *(const ulonglong2*)(ap + 4);
            unsigned long long am[4] = {a01.x, a01.y, a23.x, a23.y};
            const float* bp = &Bs[kk * LDT + tx * 8];
            float4 b0 = *(const float4*)bp;
            float4 b1 = *(const float4*)(bp + 4);
            float bb[8] = {b0.x, b0.y, b0.z, b0.w, b1.x, b1.y, b1.z, b1.w};
#pragma unroll
            for (int j = 0; j < 8; j++) {
                unsigned long long bd = f2dup(bb[j]);
#pragma unroll
                for (int i2 = 0; i2 < 4; i2++)
                    acc[i2][j] = fma2(am[i2], bd, acc[i2][j]);
            }
        }
        __syncthreads();
    }

    float w0 = 1.f, w1 = 0.f;
    if (FUSE) {
        float a = mixw[0], b = mixw[1];
        float mx = fmaxf(a, b);
        float e0 = __expf(a - mx), e1 = __expf(b - mx);
        float inv = 1.f / (e0 + e1);
        w0 = e0 * inv;
        w1 = e1 * inv;
    }

#pragma unroll
    for (int i2 = 0; i2 < 4; i2++) {
#pragma unroll
        for (int j = 0; j < 8; j++) {
            float lo, hi;
            unpk(acc[i2][j], lo, hi);
            int r = m0 + ty * 8 + 2 * i2;
            int c = n0 + tx * 8 + j;
            if (FUSE) {
                float bv = bias[c];
                Cout[(size_t)r * N + c] =
                    w0 * (lo + bv) + w1 * four[(size_t)r * N + c];
                Cout[(size_t)(r + 1) * N + c] =
                    w0 * (hi + bv) + w1 * four[(size_t)(r + 1) * N + c];
            } else {
                Cout[(size_t)r * N + c] = lo;
                Cout[(size_t)(r + 1) * N + c] = hi;
            }
        }
    }
}

// ---------------- Flash attention: per (bh, q-tile of 64) ------------------
// Q,K stored d-major (transposed) in smem for conflict-free float4 frags.
__global__ __launch_bounds__(256)
void attn_kernel(const float* __restrict__ qkv, float* __restrict__ outp) {
    extern __shared__ float sm[];
    const int P = 68;
    float* Qs = sm;                 // Qs[d*P + q]
    float* Ks = sm + 64 * P;        // Ks[d*P + k]
    float* Vs = sm + 2 * 64 * P;    // Vs[k*P + d]
    float* Ps = sm + 3 * 64 * P;    // Ps[q*P + k]

    const int tid = threadIdx.x;
    const int tx = tid & 15;
    const int ty = tid >> 4;
    const int qt = blockIdx.x;      // 0..15
    const int bh = blockIdx.y;      // 0..63
    const int b = bh >> 3;
    const int h = bh & 7;

    // Load Q tile (transposed)
#pragma unroll
    for (int it = 0; it < 4; it++) {
        int v = tid + it * 256;     // 0..1023
        int r = v >> 4;             // 0..63
        int dq = (v & 15) << 2;     // 0..60
        int n = qt * 64 + r;
        const float* src = qkv + (size_t)(b * NPIX + n) * (3 * CD) + h * HD + dq;
        float4 t = *(const float4*)src;
        Qs[(dq + 0) * P + r] = t.x;
        Qs[(dq + 1) * P + r] = t.y;
        Qs[(dq + 2) * P + r] = t.z;
        Qs[(dq + 3) * P + r] = t.w;
    }

    float o_[4][4];
    float mrow[4], lrow[4];
#pragma unroll
    for (int i = 0; i < 4; i++) {
        mrow[i] = -1e30f;
        lrow[i] = 0.f;
#pragma unroll
        for (int j = 0; j < 4; j++) o_[i][j] = 0.f;
    }

    for (int kt = 0; kt < 16; kt++) {
        __syncthreads();   // prior PV done with Vs/Ps
#pragma unroll
        for (int it = 0; it < 4; it++) {
            int v = tid + it * 256;
            int r = v >> 4;
            int dq = (v & 15) << 2;
            int n = kt * 64 + r;
            const float* base =
                qkv + (size_t)(b * NPIX + n) * (3 * CD) + h * HD + dq;
            float4 kv = *(const float4*)(base + CD);
            Ks[(dq + 0) * P + r] = kv.x;
            Ks[(dq + 1) * P + r] = kv.y;
            Ks[(dq + 2) * P + r] = kv.z;
            Ks[(dq + 3) * P + r] = kv.w;
            float4 vv = *(const float4*)(base + 2 * CD);
            *(float4*)&Vs[r * P + dq] = vv;
        }
        __syncthreads();

        float s_[4][4];
#pragma unroll
        for (int i = 0; i < 4; i++)
#pragma unroll
            for (int j = 0; j < 4; j++) s_[i][j] = 0.f;

#pragma unroll 8
        for (int d = 0; d < 64; d++) {
            float4 aa = *(const float4*)&Qs[d * P + ty * 4];
            float4 bb = *(const float4*)&Ks[d * P + tx * 4];
            float av[4] = {aa.x, aa.y, aa.z, aa.w};
            float bv[4] = {bb.x, bb.y, bb.z, bb.w};
#pragma unroll
            for (int i = 0; i < 4; i++)
#pragma unroll
                for (int j = 0; j < 4; j++) s_[i][j] += av[i] * bv[j];
        }

        // online softmax (rows reduced across the 16 tx lanes of this ty)
#pragma unroll
        for (int i = 0; i < 4; i++) {
            float rm = -1e30f;
#pragma unroll
            for (int j = 0; j < 4; j++) {
                s_[i][j] *= 0.125f;   // HEAD_DIM^-0.5
                rm = fmaxf(rm, s_[i][j]);
            }
#pragma unroll
            for (int off = 8; off > 0; off >>= 1)
                rm = fmaxf(rm, __shfl_xor_sync(0xffffffffu, rm, off));
            float mn = fmaxf(mrow[i], rm);
            float corr = __expf(mrow[i] - mn);
            mrow[i] = mn;
            float rs = 0.f;
#pragma unroll
            for (int j = 0; j < 4; j++) {
                float p = __expf(s_[i][j] - mn);
                s_[i][j] = p;
                rs += p;
            }
#pragma unroll
            for (int off = 8; off > 0; off >>= 1)
                rs += __shfl_xor_sync(0xffffffffu, rs, off);
            lrow[i] = lrow[i] * corr + rs;
#pragma unroll
            for (int j = 0; j < 4; j++) o_[i][j] *= corr;
            *(float4*)&Ps[(ty * 4 + i) * P + tx * 4] =
                make_float4(s_[i][0], s_[i][1], s_[i][2], s_[i][3]);
        }
        __syncthreads();

#pragma unroll 4
        for (int k = 0; k < 64; k++) {
            float4 vv4 = *(const float4*)&Vs[k * P + tx * 4];
            float vv[4] = {vv4.x, vv4.y, vv4.z, vv4.w};
#pragma unroll
            for (int i = 0; i < 4; i++) {
                float p = Ps[(ty * 4 + i) * P + k];
#pragma unroll
                for (int j = 0; j < 4; j++) o_[i][j] += p * vv[j];
            }
        }
    }

#pragma unroll
    for (int i = 0; i < 4; i++) {
        float inv = 1.f / lrow[i];
        int q = qt * 64 + ty * 4 + i;
        float4 w = make_float4(o_[i][0] * inv, o_[i][1] * inv, o_[i][2] * inv,
                               o_[i][3] * inv);
        *(float4*)&outp[(size_t)(b * NPIX + q) * CD + h * HD + tx * 4] = w;
    }
}

// ---------------- Fourier branch (analytically reduced) + LayerNorm --------
// irfft2(rfft2(x)*s + d) = x*s  (+ DC term at pixel (0,0) from fconv_b)
__global__ __launch_bounds__(128)
void fourier_kernel(const float* __restrict__ x,
                    const float* __restrict__ fconv_w,
                    const float* __restrict__ fconv_b,
                    const float* __restrict__ freq_w,
                    const float* __restrict__ ln_g,
                    const float* __restrict__ ln_b,
                    float* __restrict__ outp) {
    const int row = blockIdx.x;      // 0..8191 = b*1024 + pixel
    const int tid = threadIdx.x;     // 128
    const int c = tid * 4;

    float4 xv = *(const float4*)(x + (size_t)row * CD + c);
    float4 fw = *(const float4*)(freq_w + c);
    float4 cw = *(const float4*)(fconv_w + c);
    float y[4];
    y[0] = xv.x * (fw.x + 0.1f * cw.x);
    y[1] = xv.y * (fw.y + 0.1f * cw.y);
    y[2] = xv.z * (fw.z + 0.1f * cw.z);
    y[3] = xv.w * (fw.w + 0.1f * cw.w);
    if ((row & (NPIX - 1)) == 0) {
        // constant (1+1j)*0.1*fconv_b over all rfft bins -> 32*Re(d) at (0,0)
        float4 cb = *(const float4*)(fconv_b + c);
        y[0] += 3.2f * cb.x;
        y[1] += 3.2f * cb.y;
        y[2] += 3.2f * cb.z;
        y[3] += 3.2f * cb.w;
    }
    float sum = y[0] + y[1] + y[2] + y[3];
    float sq = y[0] * y[0] + y[1] * y[1] + y[2] * y[2] + y[3] * y[3];
#pragma unroll
    for (int off = 16; off > 0; off >>= 1) {
        sum += __shfl_xor_sync(0xffffffffu, sum, off);
        sq += __shfl_xor_sync(0xffffffffu, sq, off);
    }
    __shared__ float ss[4], sx[4];
    if ((tid & 31) == 0) {
        ss[tid >> 5] = sum;
        sx[tid >> 5] = sq;
    }
    __syncthreads();
    sum = ss[0] + ss[1] + ss[2] + ss[3];
    sq = sx[0] + sx[1] + sx[2] + sx[3];
    float mu = sum * (1.f / 512.f);
    float var = sq * (1.f / 512.f) - mu * mu;
    float rstd = rsqrtf(var + 1e-5f);
    float4 g = *(const float4*)(ln_g + c);
    float4 bb = *(const float4*)(ln_b + c);
    float4 o;
    o.x = (y[0] - mu) * rstd * g.x + bb.x;
    o.y = (y[1] - mu) * rstd * g.y + bb.y;
    o.z = (y[2] - mu) * rstd * g.z + bb.z;
    o.w = (y[3] - mu) * rstd * g.w + bb.w;
    *(float4*)(outp + (size_t)row * CD + c) = o;
}

// ---------------- launch ----------------------------------------------------
extern "C" void kernel_launch(void* const* d_in, const int* in_sizes, int n_in,
                              void* d_out, int out_size) {
    const float* x       = (const float*)d_in[0];
    const float* qkv_w   = (const float*)d_in[1];
    const float* proj_w  = (const float*)d_in[2];
    const float* proj_b  = (const float*)d_in[3];
    const float* fconv_w = (const float*)d_in[4];
    const float* fconv_b = (const float*)d_in[5];
    const float* freq_w  = (const float*)d_in[6];
    const float* ln_g    = (const float*)d_in[7];
    const float* ln_b    = (const float*)d_in[8];
    const float* mix_w   = (const float*)d_in[9];
    float* out = (float*)d_out;

    float *qkv_p, *attn_p, *four_p;
    cudaGetSymbolAddress((void**)&qkv_p, g_qkv);
    cudaGetSymbolAddress((void**)&attn_p, g_attn);
    cudaGetSymbolAddress((void**)&four_p, g_four);

    // 1) QKV GEMM: [8192,1536] = x[8192,512] @ qkv_w[1536,512]^T
    gemm_kernel<false><<<dim3(12, 64), 256>>>(x, qkv_w, qkv_p, 512, 1536,
                                              nullptr, nullptr, nullptr);

    // 2) Fourier branch (independent; tiny)
    fourier_kernel<<<BQ * NPIX, 128>>>(x, fconv_w, fconv_b, freq_w, ln_g,
                                       ln_b, four_p);

    // 3) Flash attention
    const int smem = 4 * 64 * 68 * (int)sizeof(float);  // 69632 B
    cudaFuncSetAttribute(attn_kernel,
                         cudaFuncAttributeMaxDynamicSharedMemorySize, smem);
    attn_kernel<<<dim3(16, 64), 256, smem>>>(qkv_p, attn_p);

    // 4) Proj GEMM + fused mix of both branches
    gemm_kernel<true><<<dim3(4, 64), 256>>>(attn_p, proj_w, out, 512, 512,
                                            proj_b, four_p, mix_w);
}

// round 3
// speedup vs baseline: 3.4625x; 3.4625x over previous
#include <cuda_runtime.h>
#include <cuda_bf16.h>
#include <cuda_fp16.h>
#include <math.h>
#include <stdint.h>

#define BQ   8
#define NPIX 1024
#define CD   512
#define NH   8
#define HD   64

// ---------------- scratch (device globals; allocation-free rule) -----------
__device__ __half g_qkvh[BQ * NPIX * 3 * CD];          // fp16 qkv [8192][1536]
__device__ float g_attn[BQ * NPIX * CD];               // [8192][512]
__device__ float g_four[BQ * NPIX * CD];               // [8192][512]
__device__ __nv_bfloat16 g_xh[BQ * NPIX * CD], g_xl[BQ * NPIX * CD];
__device__ __nv_bfloat16 g_ah[BQ * NPIX * CD], g_al[BQ * NPIX * CD];
__device__ __nv_bfloat16 g_wqh[3 * CD * CD], g_wql[3 * CD * CD];
__device__ __nv_bfloat16 g_pwh[CD * CD], g_pwl[CD * CD];

// ---------------- PTX helpers ----------------------------------------------
__device__ __forceinline__ uint32_t smem_u32(const void* p) {
    uint32_t a;
    asm("{ .reg .u64 t; cvta.to.shared.u64 t, %1; cvt.u32.u64 %0, t; }"
        : "=r"(a) : "l"(p));
    return a;
}
__device__ __forceinline__ void cp16(uint32_t dst, const void* src) {
    asm volatile("cp.async.cg.shared.global [%0], [%1], 16;"
                 :: "r"(dst), "l"(src) : "memory");
}
#define CP_COMMIT() asm volatile("cp.async.commit_group;" ::: "memory")
#define CP_WAIT0()  asm volatile("cp.async.wait_group 0;" ::: "memory")
#define CP_WAIT1()  asm volatile("cp.async.wait_group 1;" ::: "memory")

__device__ __forceinline__ void ldsm4(uint32_t (&r)[4], uint32_t a) {
    asm volatile("ldmatrix.sync.aligned.m8n8.x4.shared.b16 {%0,%1,%2,%3}, [%4];"
                 : "=r"(r[0]), "=r"(r[1]), "=r"(r[2]), "=r"(r[3]) : "r"(a));
}
__device__ __forceinline__ void ldsm4t(uint32_t (&r)[4], uint32_t a) {
    asm volatile("ldmatrix.sync.aligned.m8n8.x4.trans.shared.b16 {%0,%1,%2,%3}, [%4];"
                 : "=r"(r[0]), "=r"(r[1]), "=r"(r[2]), "=r"(r[3]) : "r"(a));
}
__device__ __forceinline__ void mma_bf16(float (&d)[4], const uint32_t (&a)[4],
                                         uint32_t b0, uint32_t b1) {
    asm volatile(
        "mma.sync.aligned.m16n8k16.row.col.f32.bf16.bf16.f32 "
        "{%0,%1,%2,%3}, {%4,%5,%6,%7}, {%8,%9}, {%0,%1,%2,%3};"
        : "+f"(d[0]), "+f"(d[1]), "+f"(d[2]), "+f"(d[3])
        : "r"(a[0]), "r"(a[1]), "r"(a[2]), "r"(a[3]), "r"(b0), "r"(b1));
}
__device__ __forceinline__ void mma_f16(float (&d)[4], const uint32_t (&a)[4],
                                        uint32_t b0, uint32_t b1) {
    asm volatile(
        "mma.sync.aligned.m16n8k16.row.col.f32.f16.f16.f32 "
        "{%0,%1,%2,%3}, {%4,%5,%6,%7}, {%8,%9}, {%0,%1,%2,%3};"
        : "+f"(d[0]), "+f"(d[1]), "+f"(d[2]), "+f"(d[3])
        : "r"(a[0]), "r"(a[1]), "r"(a[2]), "r"(a[3]), "r"(b0), "r"(b1));
}

// ---------------- fp32 -> bf16 hi/lo elementwise ---------------------------
__global__ __launch_bounds__(256)
void conv_hl(const float* __restrict__ src, __nv_bfloat16* __restrict__ dh,
             __nv_bfloat16* __restrict__ dl, int n4) {
    int i = blockIdx.x * 256 + threadIdx.x;
    if (i >= n4) return;
    float4 v = ((const float4*)src)[i];
    float e[4] = {v.x, v.y, v.z, v.w};
    union { __nv_bfloat16 b[4]; uint2 u; } H, L;
#pragma unroll
    for (int k = 0; k < 4; k++) {
        __nv_bfloat16 hb = __float2bfloat16(e[k]);
        H.b[k] = hb;
        L.b[k] = __float2bfloat16(e[k] - __bfloat162float(hb));
    }
    ((uint2*)dh)[i] = H.u;
    ((uint2*)dl)[i] = L.u;
}

// ---------------- HMMA GEMM: C[M,N] = A[M,K=512] @ B[N,K]^T (bf16 x3) ------
// 128x128 tile, BK=32, 256 threads (8 warps, 4x2), double-buffered cp.async.
// MODE 0: write fp16. MODE 1: write fp32 with bias + branch mix.
template <int MODE>
__global__ __launch_bounds__(256, 1)
void gemm_mma(const __nv_bfloat16* __restrict__ Ah,
              const __nv_bfloat16* __restrict__ Al,
              const __nv_bfloat16* __restrict__ Bh,
              const __nv_bfloat16* __restrict__ Bl,
              void* __restrict__ Cout, int N,
              const float* __restrict__ bias, const float* __restrict__ four,
              const float* __restrict__ mixw) {
    extern __shared__ __align__(16) char sm[];
    const uint32_t sbase = smem_u32(sm);
    const int tid = threadIdx.x, w = tid >> 5, lane = tid & 31;
    const int wm = w & 3, wn = w >> 2;
    const int m0 = blockIdx.y * 128, n0 = blockIdx.x * 128;

    const int lrA = lane & 15, lcA = (lane >> 4) << 3;
    const int lrB = ((lane >> 4) & 1) * 8 + (lane & 7);
    const int lcB = ((lane >> 3) & 1) * 8;

    float acc[2][8][4];
#pragma unroll
    for (int mt = 0; mt < 2; mt++)
#pragma unroll
        for (int j = 0; j < 8; j++)
#pragma unroll
            for (int r = 0; r < 4; r++) acc[mt][j][r] = 0.f;

    // stage layout: Ah @0, Al @10240, Bh @20480, Bl @30720; stride 40960
    auto load_stage = [&](int kt, int s) {
        uint32_t sb = sbase + s * 40960;
#pragma unroll
        for (int i = 0; i < 8; i++) {
            int idx = tid + i * 256;
            int mat = idx >> 9, rem = idx & 511;
            int r = rem >> 2, c = rem & 3;
            const __nv_bfloat16* g =
                (mat == 0) ? Ah : (mat == 1) ? Al : (mat == 2) ? Bh : Bl;
            int rowbase = (mat < 2) ? m0 : n0;
            const void* src = g + (size_t)(rowbase + r) * 512 + kt * 32 + c * 8;
            cp16(sb + mat * 10240 + (r * 40 + c * 8) * 2, src);
        }
    };

    load_stage(0, 0);
    CP_COMMIT();

    for (int kt = 0; kt < 16; kt++) {
        if (kt < 15) {
            load_stage(kt + 1, (kt + 1) & 1);
            CP_COMMIT();
            CP_WAIT1();
        } else {
            CP_WAIT0();
        }
        __syncthreads();

        uint32_t sb = sbase + (kt & 1) * 40960;
#pragma unroll
        for (int ks = 0; ks < 2; ks++) {
            uint32_t ah[2][4], al[2][4];
#pragma unroll
            for (int mt = 0; mt < 2; mt++) {
                uint32_t off =
                    ((wm * 32 + mt * 16 + lrA) * 40 + ks * 16 + lcA) * 2;
                ldsm4(ah[mt], sb + off);
                ldsm4(al[mt], sb + 10240 + off);
            }
            uint32_t bh[4][4], bl[4][4];
#pragma unroll
            for (int g = 0; g < 4; g++) {
                uint32_t off =
                    ((wn * 64 + g * 16 + lrB) * 40 + ks * 16 + lcB) * 2;
                ldsm4(bh[g], sb + 20480 + off);
                ldsm4(bl[g], sb + 30720 + off);
            }
#pragma unroll
            for (int mt = 0; mt < 2; mt++)
#pragma unroll
                for (int g = 0; g < 4; g++) {
                    mma_bf16(acc[mt][2 * g], ah[mt], bh[g][0], bh[g][1]);
                    mma_bf16(acc[mt][2 * g + 1], ah[mt], bh[g][2], bh[g][3]);
                    mma_bf16(acc[mt][2 * g], al[mt], bh[g][0], bh[g][1]);
                    mma_bf16(acc[mt][2 * g + 1], al[mt], bh[g][2], bh[g][3]);
                    mma_bf16(acc[mt][2 * g], ah[mt], bl[g][0], bl[g][1]);
                    mma_bf16(acc[mt][2 * g + 1], ah[mt], bl[g][2], bl[g][3]);
                }
        }
        __syncthreads();
    }

    // epilogue
    float w0 = 1.f, w1 = 0.f;
    if (MODE == 1) {
        float a = mixw[0], b = mixw[1];
        float mx = fmaxf(a, b);
        float e0 = __expf(a - mx), e1 = __expf(b - mx);
        float inv = 1.f / (e0 + e1);
        w0 = e0 * inv;
        w1 = e1 * inv;
    }
#pragma unroll
    for (int mt = 0; mt < 2; mt++) {
        int r0 = m0 + wm * 32 + mt * 16 + (lane >> 2);
        int r1 = r0 + 8;
#pragma unroll
        for (int j = 0; j < 8; j++) {
            int col = n0 + wn * 64 + j * 8 + (lane & 3) * 2;
            if (MODE == 0) {
                __half* O = (__half*)Cout;
                *(__half2*)(O + (size_t)r0 * N + col) =
                    __float22half2_rn(make_float2(acc[mt][j][0], acc[mt][j][1]));
                *(__half2*)(O + (size_t)r1 * N + col) =
                    __float22half2_rn(make_float2(acc[mt][j][2], acc[mt][j][3]));
            } else {
                float* O = (float*)Cout;
                float b0 = bias[col], b1 = bias[col + 1];
                const float* f0 = four + (size_t)r0 * N + col;
                const float* f1 = four + (size_t)r1 * N + col;
                float2 o0, o1;
                o0.x = w0 * (acc[mt][j][0] + b0) + w1 * f0[0];
                o0.y = w0 * (acc[mt][j][1] + b1) + w1 * f0[1];
                o1.x = w0 * (acc[mt][j][2] + b0) + w1 * f1[0];
                o1.y = w0 * (acc[mt][j][3] + b1) + w1 * f1[1];
                *(float2*)(O + (size_t)r0 * N + col) = o0;
                *(float2*)(O + (size_t)r1 * N + col) = o1;
            }
        }
    }
}

// ---------------- FA2-style fp16 HMMA flash attention -----------------------
// 128 threads (4 warps), q-tile 64 (16 per warp), k-tiles of 64, 16 iters.
__global__ __launch_bounds__(128)
void attn_mma(const __half* __restrict__ qkvh, float* __restrict__ outp) {
    __shared__ __align__(16) __half sQ[64 * 72];
    __shared__ __align__(16) __half sKV[2][2][64 * 72];

    const int tid = threadIdx.x, w = tid >> 5, lane = tid & 31;
    const int qt = blockIdx.x, bh = blockIdx.y;
    const int b = bh >> 3, h = bh & 7;
    const __half* base = qkvh + (size_t)b * NPIX * 1536 + h * 64;

    const uint32_t sQa = smem_u32(sQ);
    const uint32_t sKVa = smem_u32(sKV);

    const int lrA = lane & 15, lcA = (lane >> 4) << 3;
    const int lrB = ((lane >> 4) & 1) * 8 + (lane & 7);
    const int lcB = ((lane >> 3) & 1) * 8;
    const int lrV = ((lane >> 3) & 1) * 8 + (lane & 7);
    const int lcV = ((lane >> 4) & 1) * 8;

    // prologue loads: Q tile + K0/V0
#pragma unroll
    for (int i = 0; i < 4; i++) {
        int idx = tid + i * 128;
        int r = idx >> 3, c = idx & 7;
        cp16(sQa + (r * 72 + c * 8) * 2,
             base + (size_t)(qt * 64 + r) * 1536 + c * 8);
    }
#pragma unroll
    for (int i = 0; i < 8; i++) {
        int idx = tid + i * 128;
        int m = idx >> 9, rem = idx & 511;
        int r = rem >> 3, c = rem & 7;
        cp16(sKVa + (m * 4608 + r * 72 + c * 8) * 2,
             base + (size_t)r * 1536 + 512 + m * 512 + c * 8);
    }
    CP_COMMIT();

    float oacc[8][4];
#pragma unroll
    for (int j = 0; j < 8; j++)
#pragma unroll
        for (int r = 0; r < 4; r++) oacc[j][r] = 0.f;
    float m0 = -1e30f, m1 = -1e30f, l0 = 0.f, l1 = 0.f;
    uint32_t qf[4][4];
    const float SC = 0.125f * 1.44269504f;   // scale * log2(e)

    for (int kt = 0; kt < 16; kt++) {
        if (kt < 15) {
            int nb = (kt + 1) & 1;
#pragma unroll
            for (int i = 0; i < 8; i++) {
                int idx = tid + i * 128;
                int m = idx >> 9, rem = idx & 511;
                int r = rem >> 3, c = rem & 7;
                cp16(sKVa + ((nb * 2 + m) * 4608 + r * 72 + c * 8) * 2,
                     base + (size_t)((kt + 1) * 64 + r) * 1536 + 512 + m * 512 +
                         c * 8);
            }
            CP_COMMIT();
            CP_WAIT1();
        } else {
            CP_WAIT0();
        }
        __syncthreads();

        if (kt == 0) {
#pragma unroll
            for (int ds = 0; ds < 4; ds++)
                ldsm4(qf[ds],
                      sQa + ((w * 16 + lrA) * 72 + ds * 16 + lcA) * 2);
        }

        const uint32_t sK = sKVa + ((kt & 1) * 2 + 0) * 4608 * 2;
        const uint32_t sV = sKVa + ((kt & 1) * 2 + 1) * 4608 * 2;

        // ---- S = Q K^T ----
        float sacc[8][4];
#pragma unroll
        for (int j = 0; j < 8; j++)
#pragma unroll
            for (int r = 0; r < 4; r++) sacc[j][r] = 0.f;
#pragma unroll
        for (int ds = 0; ds < 4; ds++) {
#pragma unroll
            for (int g = 0; g < 4; g++) {
                uint32_t kb[4];
                ldsm4(kb, sK + ((g * 16 + lrB) * 72 + ds * 16 + lcB) * 2);
                mma_f16(sacc[2 * g], qf[ds], kb[0], kb[1]);
                mma_f16(sacc[2 * g + 1], qf[ds], kb[2], kb[3]);
            }
        }

        // ---- online softmax (exp2 domain) ----
        float rm0 = -1e30f, rm1 = -1e30f;
#pragma unroll
        for (int j = 0; j < 8; j++) {
#pragma unroll
            for (int r = 0; r < 4; r++) sacc[j][r] *= SC;
            rm0 = fmaxf(rm0, fmaxf(sacc[j][0], sacc[j][1]));
            rm1 = fmaxf(rm1, fmaxf(sacc[j][2], sacc[j][3]));
        }
        rm0 = fmaxf(rm0, __shfl_xor_sync(0xffffffffu, rm0, 1));
        rm0 = fmaxf(rm0, __shfl_xor_sync(0xffffffffu, rm0, 2));
        rm1 = fmaxf(rm1, __shfl_xor_sync(0xffffffffu, rm1, 1));
        rm1 = fmaxf(rm1, __shfl_xor_sync(0xffffffffu, rm1, 2));
        float mn0 = fmaxf(m0, rm0), mn1 = fmaxf(m1, rm1);
        float a0 = exp2f(m0 - mn0), a1 = exp2f(m1 - mn1);
        m0 = mn0;
        m1 = mn1;

        float rs0 = 0.f, rs1 = 0.f;
        uint32_t pf[4][4];
#pragma unroll
        for (int j = 0; j < 8; j++) {
            float p0 = exp2f(sacc[j][0] - mn0);
            float p1 = exp2f(sacc[j][1] - mn0);
            float p2 = exp2f(sacc[j][2] - mn1);
            float p3 = exp2f(sacc[j][3] - mn1);
            rs0 += p0 + p1;
            rs1 += p2 + p3;
            int ks = j >> 1, t = (j & 1) * 2;
            pf[ks][t] = __half2_raw(__float22half2_rn(make_float2(p0, p1))).x |
                        ((uint32_t)__half2_raw(
                             __float22half2_rn(make_float2(p0, p1))).y
                         << 16);
            // simpler & correct packing:
            __half2 h01 = __float22half2_rn(make_float2(p0, p1));
            __half2 h23 = __float22half2_rn(make_float2(p2, p3));
            pf[ks][t] = *(uint32_t*)&h01;
            pf[ks][t + 1] = *(uint32_t*)&h23;
        }
        rs0 += __shfl_xor_sync(0xffffffffu, rs0, 1);
        rs0 += __shfl_xor_sync(0xffffffffu, rs0, 2);
        rs1 += __shfl_xor_sync(0xffffffffu, rs1, 1);
        rs1 += __shfl_xor_sync(0xffffffffu, rs1, 2);
        l0 = l0 * a0 + rs0;
        l1 = l1 * a1 + rs1;
#pragma unroll
        for (int j = 0; j < 8; j++) {
            oacc[j][0] *= a0;
            oacc[j][1] *= a0;
            oacc[j][2] *= a1;
            oacc[j][3] *= a1;
        }

        // ---- O += P V ----
#pragma unroll
        for (int ks = 0; ks < 4; ks++) {
#pragma unroll
            for (int gd = 0; gd < 4; gd++) {
                uint32_t vb[4];
                ldsm4t(vb, sV + ((ks * 16 + lrV) * 72 + gd * 16 + lcV) * 2);
                mma_f16(oacc[2 * gd], pf[ks], vb[0], vb[1]);
                mma_f16(oacc[2 * gd + 1], pf[ks], vb[2], vb[3]);
            }
        }
        __syncthreads();
    }

    float inv0 = 1.f / l0, inv1 = 1.f / l1;
    int r0 = qt * 64 + w * 16 + (lane >> 2);
    int r1 = r0 + 8;
    float* o0 = outp + (size_t)(b * NPIX + r0) * CD + h * 64 + (lane & 3) * 2;
    float* o1 = outp + (size_t)(b * NPIX + r1) * CD + h * 64 + (lane & 3) * 2;
#pragma unroll
    for (int j = 0; j < 8; j++) {
        *(float2*)(o0 + j * 8) =
            make_float2(oacc[j][0] * inv0, oacc[j][1] * inv0);
        *(float2*)(o1 + j * 8) =
            make_float2(oacc[j][2] * inv1, oacc[j][3] * inv1);
    }
}

// ---------------- Fourier branch (analytically reduced) + LayerNorm --------
__global__ __launch_bounds__(128)
void fourier_kernel(const float* __restrict__ x,
                    const float* __restrict__ fconv_w,
                    const float* __restrict__ fconv_b,
                    const float* __restrict__ freq_w,
                    const float* __restrict__ ln_g,
                    const float* __restrict__ ln_b,
                    float* __restrict__ outp) {
    const int row = blockIdx.x;
    const int tid = threadIdx.x;
    const int c = tid * 4;

    float4 xv = *(const float4*)(x + (size_t)row * CD + c);
    float4 fw = *(const float4*)(freq_w + c);
    float4 cw = *(const float4*)(fconv_w + c);
    float y[4];
    y[0] = xv.x * (fw.x + 0.1f * cw.x);
    y[1] = xv.y * (fw.y + 0.1f * cw.y);
    y[2] = xv.z * (fw.z + 0.1f * cw.z);
    y[3] = xv.w * (fw.w + 0.1f * cw.w);
    if ((row & (NPIX - 1)) == 0) {
        float4 cb = *(const float4*)(fconv_b + c);
        y[0] += 3.2f * cb.x;
        y[1] += 3.2f * cb.y;
        y[2] += 3.2f * cb.z;
        y[3] += 3.2f * cb.w;
    }
    float sum = y[0] + y[1] + y[2] + y[3];
    float sq = y[0] * y[0] + y[1] * y[1] + y[2] * y[2] + y[3] * y[3];
#pragma unroll
    for (int off = 16; off > 0; off >>= 1) {
        sum += __shfl_xor_sync(0xffffffffu, sum, off);
        sq += __shfl_xor_sync(0xffffffffu, sq, off);
    }
    __shared__ float ss[4], sx[4];
    if ((tid & 31) == 0) {
        ss[tid >> 5] = sum;
        sx[tid >> 5] = sq;
    }
    __syncthreads();
    sum = ss[0] + ss[1] + ss[2] + ss[3];
    sq = sx[0] + sx[1] + sx[2] + sx[3];
    float mu = sum * (1.f / 512.f);
    float var = sq * (1.f / 512.f) - mu * mu;
    float rstd = rsqrtf(var + 1e-5f);
    float4 g = *(const float4*)(ln_g + c);
    float4 bb = *(const float4*)(ln_b + c);
    float4 o;
    o.x = (y[0] - mu) * rstd * g.x + bb.x;
    o.y = (y[1] - mu) * rstd * g.y + bb.y;
    o.z = (y[2] - mu) * rstd * g.z + bb.z;
    o.w = (y[3] - mu) * rstd * g.w + bb.w;
    *(float4*)(outp + (size_t)row * CD + c) = o;
}

// ---------------- launch ----------------------------------------------------
extern "C" void kernel_launch(void* const* d_in, const int* in_sizes, int n_in,
                              void* d_out, int out_size) {
    const float* x       = (const float*)d_in[0];
    const float* qkv_w   = (const float*)d_in[1];
    const float* proj_w  = (const float*)d_in[2];
    const float* proj_b  = (const float*)d_in[3];
    const float* fconv_w = (const float*)d_in[4];
    const float* fconv_b = (const float*)d_in[5];
    const float* freq_w  = (const float*)d_in[6];
    const float* ln_g    = (const float*)d_in[7];
    const float* ln_b    = (const float*)d_in[8];
    const float* mix_w   = (const float*)d_in[9];
    float* out = (float*)d_out;

    __half* qkvh;
    float *attn_p, *four_p;
    __nv_bfloat16 *xh, *xl, *ah, *al, *wqh, *wql, *pwh, *pwl;
    cudaGetSymbolAddress((void**)&qkvh, g_qkvh);
    cudaGetSymbolAddress((void**)&attn_p, g_attn);
    cudaGetSymbolAddress((void**)&four_p, g_four);
    cudaGetSymbolAddress((void**)&xh, g_xh);
    cudaGetSymbolAddress((void**)&xl, g_xl);
    cudaGetSymbolAddress((void**)&ah, g_ah);
    cudaGetSymbolAddress((void**)&al, g_al);
    cudaGetSymbolAddress((void**)&wqh, g_wqh);
    cudaGetSymbolAddress((void**)&wql, g_wql);
    cudaGetSymbolAddress((void**)&pwh, g_pwh);
    cudaGetSymbolAddress((void**)&pwl, g_pwl);

    const int GEMM_SMEM = 2 * 40960;   // 81920
    cudaFuncSetAttribute(gemm_mma<0>,
                         cudaFuncAttributeMaxDynamicSharedMemorySize, GEMM_SMEM);
    cudaFuncSetAttribute(gemm_mma<1>,
                         cudaFuncAttributeMaxDynamicSharedMemorySize, GEMM_SMEM);

    // 1) converts
    conv_hl<<<4096, 256>>>(x, xh, xl, BQ * NPIX * CD / 4);
    conv_hl<<<768, 256>>>(qkv_w, wqh, wql, 3 * CD * CD / 4);
    conv_hl<<<256, 256>>>(proj_w, pwh, pwl, CD * CD / 4);

    // 2) QKV GEMM (HMMA bf16 x3), fp16 output
    gemm_mma<0><<<dim3(12, 64), 256, GEMM_SMEM>>>(
        xh, xl, wqh, wql, qkvh, 1536, nullptr, nullptr, nullptr);

    // 3) Fourier branch
    fourier_kernel<<<BQ * NPIX, 128>>>(x, fconv_w, fconv_b, freq_w, ln_g,
                                       ln_b, four_p);

    // 4) flash attention (fp16 HMMA)
    attn_mma<<<dim3(16, 64), 128>>>(qkvh, attn_p);

    // 5) convert attention output
    conv_hl<<<4096, 256>>>(attn_p, ah, al, BQ * NPIX * CD / 4);

    // 6) proj GEMM + fused mix
    gemm_mma<1><<<dim3(4, 64), 256, GEMM_SMEM>>>(
        ah, al, pwh, pwl, out, 512, proj_b, four_p, mix_w);
}

// round 4
// speedup vs baseline: 3.4841x; 1.0062x over previous
#include <cuda_runtime.h>
#include <cuda_bf16.h>
#include <cuda_fp16.h>
#include <math.h>
#include <stdint.h>

#define BQ   8
#define NPIX 1024
#define CD   512
#define NH   8
#define HD   64

// ---------------- scratch (device globals; allocation-free rule) -----------
__device__ __half g_qkvh[BQ * NPIX * 3 * CD];          // fp16 qkv [8192][1536]
__device__ float g_four[BQ * NPIX * CD];               // [8192][512]
__device__ __nv_bfloat16 g_xh[BQ * NPIX * CD], g_xl[BQ * NPIX * CD];
__device__ __nv_bfloat16 g_ah[BQ * NPIX * CD], g_al[BQ * NPIX * CD];
__device__ __nv_bfloat16 g_wqh[3 * CD * CD], g_wql[3 * CD * CD];
__device__ __nv_bfloat16 g_pwh[CD * CD], g_pwl[CD * CD];

// ---------------- PTX helpers ----------------------------------------------
__device__ __forceinline__ uint32_t smem_u32(const void* p) {
    uint32_t a;
    asm("{ .reg .u64 t; cvta.to.shared.u64 t, %1; cvt.u32.u64 %0, t; }"
        : "=r"(a) : "l"(p));
    return a;
}
__device__ __forceinline__ void cp16(uint32_t dst, const void* src) {
    asm volatile("cp.async.cg.shared.global [%0], [%1], 16;"
                 :: "r"(dst), "l"(src) : "memory");
}
#define CP_COMMIT() asm volatile("cp.async.commit_group;" ::: "memory")
#define CP_WAIT0()  asm volatile("cp.async.wait_group 0;" ::: "memory")
#define CP_WAIT1()  asm volatile("cp.async.wait_group 1;" ::: "memory")
#define CP_WAIT2()  asm volatile("cp.async.wait_group 2;" ::: "memory")

__device__ __forceinline__ void ldsm4(uint32_t (&r)[4], uint32_t a) {
    asm volatile("ldmatrix.sync.aligned.m8n8.x4.shared.b16 {%0,%1,%2,%3}, [%4];"
                 : "=r"(r[0]), "=r"(r[1]), "=r"(r[2]), "=r"(r[3]) : "r"(a));
}
__device__ __forceinline__ void ldsm4t(uint32_t (&r)[4], uint32_t a) {
    asm volatile("ldmatrix.sync.aligned.m8n8.x4.trans.shared.b16 {%0,%1,%2,%3}, [%4];"
                 : "=r"(r[0]), "=r"(r[1]), "=r"(r[2]), "=r"(r[3]) : "r"(a));
}
__device__ __forceinline__ void mma_bf16(float (&d)[4], const uint32_t (&a)[4],
                                         uint32_t b0, uint32_t b1) {
    asm volatile(
        "mma.sync.aligned.m16n8k16.row.col.f32.bf16.bf16.f32 "
        "{%0,%1,%2,%3}, {%4,%5,%6,%7}, {%8,%9}, {%0,%1,%2,%3};"
        : "+f"(d[0]), "+f"(d[1]), "+f"(d[2]), "+f"(d[3])
        : "r"(a[0]), "r"(a[1]), "r"(a[2]), "r"(a[3]), "r"(b0), "r"(b1));
}
__device__ __forceinline__ void mma_f16(float (&d)[4], const uint32_t (&a)[4],
                                        uint32_t b0, uint32_t b1) {
    asm volatile(
        "mma.sync.aligned.m16n8k16.row.col.f32.f16.f16.f32 "
        "{%0,%1,%2,%3}, {%4,%5,%6,%7}, {%8,%9}, {%0,%1,%2,%3};"
        : "+f"(d[0]), "+f"(d[1]), "+f"(d[2]), "+f"(d[3])
        : "r"(a[0]), "r"(a[1]), "r"(a[2]), "r"(a[3]), "r"(b0), "r"(b1));
}

// ---------------- fp32 -> bf16 hi/lo elementwise ---------------------------
__global__ __launch_bounds__(256)
void conv_hl(const float* __restrict__ src, __nv_bfloat16* __restrict__ dh,
             __nv_bfloat16* __restrict__ dl, int n4) {
    int i = blockIdx.x * 256 + threadIdx.x;
    if (i >= n4) return;
    float4 v = ((const float4*)src)[i];
    float e[4] = {v.x, v.y, v.z, v.w};
    union { __nv_bfloat16 b[4]; uint2 u; } H, L;
#pragma unroll
    for (int k = 0; k < 4; k++) {
        __nv_bfloat16 hb = __float2bfloat16(e[k]);
        H.b[k] = hb;
        L.b[k] = __float2bfloat16(e[k] - __bfloat162float(hb));
    }
    ((uint2*)dh)[i] = H.u;
    ((uint2*)dl)[i] = L.u;
}

// ---------------- HMMA GEMM: C[M,N] = A[M,K=512] @ B[N,K]^T (bf16 x3) ------
// 128x128 tile, BK=32, 256 threads (8 warps: 2 in M x 4 in N, warp tile 64x32),
// 4-stage cp.async pipeline. MODE 0: fp16 out. MODE 1: fp32 + bias + mix.
template <int MODE>
__global__ __launch_bounds__(256, 1)
void gemm_mma(const __nv_bfloat16* __restrict__ Ah,
              const __nv_bfloat16* __restrict__ Al,
              const __nv_bfloat16* __restrict__ Bh,
              const __nv_bfloat16* __restrict__ Bl,
              void* __restrict__ Cout, int N,
              const float* __restrict__ bias, const float* __restrict__ four,
              const float* __restrict__ mixw) {
    extern __shared__ __align__(16) char sm[];
    const uint32_t sbase = smem_u32(sm);
    const int tid = threadIdx.x, w = tid >> 5, lane = tid & 31;
    const int wm = w & 1, wn = w >> 1;          // 2 x 4 warps
    const int m0 = blockIdx.y * 128, n0 = blockIdx.x * 128;

    const int lrA = lane & 15, lcA = (lane >> 4) << 3;
    const int lrB = ((lane >> 4) & 1) * 8 + (lane & 7);
    const int lcB = ((lane >> 3) & 1) * 8;

    float acc[4][4][4];                          // [mt][j][frag]
#pragma unroll
    for (int mt = 0; mt < 4; mt++)
#pragma unroll
        for (int j = 0; j < 4; j++)
#pragma unroll
            for (int r = 0; r < 4; r++) acc[mt][j][r] = 0.f;

    // stage: Ah @0, Al @10240, Bh @20480, Bl @30720 ; stride 40960, 4 stages
    auto load_stage = [&](int kt) {
        uint32_t sb = sbase + (kt & 3) * 40960;
#pragma unroll
        for (int i = 0; i < 8; i++) {
            int idx = tid + i * 256;
            int mat = idx >> 9, rem = idx & 511;
            int r = rem >> 2, c = rem & 3;
            const __nv_bfloat16* g =
                (mat == 0) ? Ah : (mat == 1) ? Al : (mat == 2) ? Bh : Bl;
            int rowbase = (mat < 2) ? m0 : n0;
            const void* src = g + (size_t)(rowbase + r) * 512 + kt * 32 + c * 8;
            cp16(sb + mat * 10240 + (r * 40 + c * 8) * 2, src);
        }
    };

    load_stage(0);
    CP_COMMIT();
    load_stage(1);
    CP_COMMIT();

    for (int kt = 0; kt < 16; kt++) {
        if (kt < 14) {
            load_stage(kt + 2);
            CP_COMMIT();
            CP_WAIT2();
        } else {
            CP_WAIT0();
        }
        __syncthreads();

        uint32_t sb = sbase + (kt & 3) * 40960;
#pragma unroll
        for (int ks = 0; ks < 2; ks++) {
            uint32_t ah[4][4], al[4][4];
#pragma unroll
            for (int mt = 0; mt < 4; mt++) {
                uint32_t off =
                    ((wm * 64 + mt * 16 + lrA) * 40 + ks * 16 + lcA) * 2;
                ldsm4(ah[mt], sb + off);
                ldsm4(al[mt], sb + 10240 + off);
            }
            uint32_t bh[2][4], bl[2][4];
#pragma unroll
            for (int g = 0; g < 2; g++) {
                uint32_t off =
                    ((wn * 32 + g * 16 + lrB) * 40 + ks * 16 + lcB) * 2;
                ldsm4(bh[g], sb + 20480 + off);
                ldsm4(bl[g], sb + 30720 + off);
            }
            // product groups ordered so each acc has RAW distance 16 MMAs
#pragma unroll
            for (int mt = 0; mt < 4; mt++)
#pragma unroll
                for (int g = 0; g < 2; g++) {
                    mma_bf16(acc[mt][2 * g], ah[mt], bh[g][0], bh[g][1]);
                    mma_bf16(acc[mt][2 * g + 1], ah[mt], bh[g][2], bh[g][3]);
                }
#pragma unroll
            for (int mt = 0; mt < 4; mt++)
#pragma unroll
                for (int g = 0; g < 2; g++) {
                    mma_bf16(acc[mt][2 * g], al[mt], bh[g][0], bh[g][1]);
                    mma_bf16(acc[mt][2 * g + 1], al[mt], bh[g][2], bh[g][3]);
                }
#pragma unroll
            for (int mt = 0; mt < 4; mt++)
#pragma unroll
                for (int g = 0; g < 2; g++) {
                    mma_bf16(acc[mt][2 * g], ah[mt], bl[g][0], bl[g][1]);
                    mma_bf16(acc[mt][2 * g + 1], ah[mt], bl[g][2], bl[g][3]);
                }
        }
        __syncthreads();
    }

    float w0 = 1.f, w1 = 0.f;
    if (MODE == 1) {
        float a = mixw[0], b = mixw[1];
        float mx = fmaxf(a, b);
        float e0 = __expf(a - mx), e1 = __expf(b - mx);
        float inv = 1.f / (e0 + e1);
        w0 = e0 * inv;
        w1 = e1 * inv;
    }
#pragma unroll
    for (int mt = 0; mt < 4; mt++) {
        int r0 = m0 + wm * 64 + mt * 16 + (lane >> 2);
        int r1 = r0 + 8;
#pragma unroll
        for (int j = 0; j < 4; j++) {
            int col = n0 + wn * 32 + j * 8 + (lane & 3) * 2;
            if (MODE == 0) {
                __half* O = (__half*)Cout;
                *(__half2*)(O + (size_t)r0 * N + col) =
                    __float22half2_rn(make_float2(acc[mt][j][0], acc[mt][j][1]));
                *(__half2*)(O + (size_t)r1 * N + col) =
                    __float22half2_rn(make_float2(acc[mt][j][2], acc[mt][j][3]));
            } else {
                float* O = (float*)Cout;
                float b0 = bias[col], b1 = bias[col + 1];
                const float* f0 = four + (size_t)r0 * N + col;
                const float* f1 = four + (size_t)r1 * N + col;
                float2 o0, o1;
                o0.x = w0 * (acc[mt][j][0] + b0) + w1 * f0[0];
                o0.y = w0 * (acc[mt][j][1] + b1) + w1 * f0[1];
                o1.x = w0 * (acc[mt][j][2] + b0) + w1 * f1[0];
                o1.y = w0 * (acc[mt][j][3] + b1) + w1 * f1[1];
                *(float2*)(O + (size_t)r0 * N + col) = o0;
                *(float2*)(O + (size_t)r1 * N + col) = o1;
            }
        }
    }
}

// ---------------- FA2-style fp16 HMMA flash attention -----------------------
// Epilogue writes bf16 hi/lo directly for the proj GEMM.
__global__ __launch_bounds__(128)
void attn_mma(const __half* __restrict__ qkvh,
              __nv_bfloat16* __restrict__ oh, __nv_bfloat16* __restrict__ ol) {
    __shared__ __align__(16) __half sQ[64 * 72];
    __shared__ __align__(16) __half sKV[2][2][64 * 72];

    const int tid = threadIdx.x, w = tid >> 5, lane = tid & 31;
    const int qt = blockIdx.x, bh = blockIdx.y;
    const int b = bh >> 3, h = bh & 7;
    const __half* base = qkvh + (size_t)b * NPIX * 1536 + h * 64;

    const uint32_t sQa = smem_u32(sQ);
    const uint32_t sKVa = smem_u32(sKV);

    const int lrA = lane & 15, lcA = (lane >> 4) << 3;
    const int lrB = ((lane >> 4) & 1) * 8 + (lane & 7);
    const int lcB = ((lane >> 3) & 1) * 8;
    const int lrV = ((lane >> 3) & 1) * 8 + (lane & 7);
    const int lcV = ((lane >> 4) & 1) * 8;

#pragma unroll
    for (int i = 0; i < 4; i++) {
        int idx = tid + i * 128;
        int r = idx >> 3, c = idx & 7;
        cp16(sQa + (r * 72 + c * 8) * 2,
             base + (size_t)(qt * 64 + r) * 1536 + c * 8);
    }
#pragma unroll
    for (int i = 0; i < 8; i++) {
        int idx = tid + i * 128;
        int m = idx >> 9, rem = idx & 511;
        int r = rem >> 3, c = rem & 7;
        cp16(sKVa + (m * 4608 + r * 72 + c * 8) * 2,
             base + (size_t)r * 1536 + 512 + m * 512 + c * 8);
    }
    CP_COMMIT();

    float oacc[8][4];
#pragma unroll
    for (int j = 0; j < 8; j++)
#pragma unroll
        for (int r = 0; r < 4; r++) oacc[j][r] = 0.f;
    float m0 = -1e30f, m1 = -1e30f, l0 = 0.f, l1 = 0.f;
    uint32_t qf[4][4];
    const float SC = 0.125f * 1.44269504f;

    for (int kt = 0; kt < 16; kt++) {
        if (kt < 15) {
            int nb = (kt + 1) & 1;
#pragma unroll
            for (int i = 0; i < 8; i++) {
                int idx = tid + i * 128;
                int m = idx >> 9, rem = idx & 511;
                int r = rem >> 3, c = rem & 7;
                cp16(sKVa + ((nb * 2 + m) * 4608 + r * 72 + c * 8) * 2,
                     base + (size_t)((kt + 1) * 64 + r) * 1536 + 512 + m * 512 +
                         c * 8);
            }
            CP_COMMIT();
            CP_WAIT1();
        } else {
            CP_WAIT0();
        }
        __syncthreads();

        if (kt == 0) {
#pragma unroll
            for (int ds = 0; ds < 4; ds++)
                ldsm4(qf[ds], sQa + ((w * 16 + lrA) * 72 + ds * 16 + lcA) * 2);
        }

        const uint32_t sK = sKVa + ((kt & 1) * 2 + 0) * 4608 * 2;
        const uint32_t sV = sKVa + ((kt & 1) * 2 + 1) * 4608 * 2;

        float sacc[8][4];
#pragma unroll
        for (int j = 0; j < 8; j++)
#pragma unroll
            for (int r = 0; r < 4; r++) sacc[j][r] = 0.f;
#pragma unroll
        for (int ds = 0; ds < 4; ds++) {
#pragma unroll
            for (int g = 0; g < 4; g++) {
                uint32_t kb[4];
                ldsm4(kb, sK + ((g * 16 + lrB) * 72 + ds * 16 + lcB) * 2);
                mma_f16(sacc[2 * g], qf[ds], kb[0], kb[1]);
                mma_f16(sacc[2 * g + 1], qf[ds], kb[2], kb[3]);
            }
        }

        float rm0 = -1e30f, rm1 = -1e30f;
#pragma unroll
        for (int j = 0; j < 8; j++) {
#pragma unroll
            for (int r = 0; r < 4; r++) sacc[j][r] *= SC;
            rm0 = fmaxf(rm0, fmaxf(sacc[j][0], sacc[j][1]));
            rm1 = fmaxf(rm1, fmaxf(sacc[j][2], sacc[j][3]));
        }
        rm0 = fmaxf(rm0, __shfl_xor_sync(0xffffffffu, rm0, 1));
        rm0 = fmaxf(rm0, __shfl_xor_sync(0xffffffffu, rm0, 2));
        rm1 = fmaxf(rm1, __shfl_xor_sync(0xffffffffu, rm1, 1));
        rm1 = fmaxf(rm1, __shfl_xor_sync(0xffffffffu, rm1, 2));
        float mn0 = fmaxf(m0, rm0), mn1 = fmaxf(m1, rm1);
        float a0 = exp2f(m0 - mn0), a1 = exp2f(m1 - mn1);
        m0 = mn0;
        m1 = mn1;

        float rs0 = 0.f, rs1 = 0.f;
        uint32_t pf[4][4];
#pragma unroll
        for (int j = 0; j < 8; j++) {
            float p0 = exp2f(sacc[j][0] - mn0);
            float p1 = exp2f(sacc[j][1] - mn0);
            float p2 = exp2f(sacc[j][2] - mn1);
            float p3 = exp2f(sacc[j][3] - mn1);
            rs0 += p0 + p1;
            rs1 += p2 + p3;
            int ks = j >> 1, t = (j & 1) * 2;
            __half2 h01 = __float22half2_rn(make_float2(p0, p1));
            __half2 h23 = __float22half2_rn(make_float2(p2, p3));
            pf[ks][t] = *(uint32_t*)&h01;
            pf[ks][t + 1] = *(uint32_t*)&h23;
        }
        rs0 += __shfl_xor_sync(0xffffffffu, rs0, 1);
        rs0 += __shfl_xor_sync(0xffffffffu, rs0, 2);
        rs1 += __shfl_xor_sync(0xffffffffu, rs1, 1);
        rs1 += __shfl_xor_sync(0xffffffffu, rs1, 2);
        l0 = l0 * a0 + rs0;
        l1 = l1 * a1 + rs1;
#pragma unroll
        for (int j = 0; j < 8; j++) {
            oacc[j][0] *= a0;
            oacc[j][1] *= a0;
            oacc[j][2] *= a1;
            oacc[j][3] *= a1;
        }

#pragma unroll
        for (int ks = 0; ks < 4; ks++) {
#pragma unroll
            for (int gd = 0; gd < 4; gd++) {
                uint32_t vb[4];
                ldsm4t(vb, sV + ((ks * 16 + lrV) * 72 + gd * 16 + lcV) * 2);
                mma_f16(oacc[2 * gd], pf[ks], vb[0], vb[1]);
                mma_f16(oacc[2 * gd + 1], pf[ks], vb[2], vb[3]);
            }
        }
        __syncthreads();
    }

    float inv0 = 1.f / l0, inv1 = 1.f / l1;
    int r0 = qt * 64 + w * 16 + (lane >> 2);
    int r1 = r0 + 8;
    size_t base0 = (size_t)(b * NPIX + r0) * CD + h * 64 + (lane & 3) * 2;
    size_t base1 = (size_t)(b * NPIX + r1) * CD + h * 64 + (lane & 3) * 2;
#pragma unroll
    for (int j = 0; j < 8; j++) {
        float u0 = oacc[j][0] * inv0, u1 = oacc[j][1] * inv0;
        float v0 = oacc[j][2] * inv1, v1 = oacc[j][3] * inv1;
        __nv_bfloat16 h0 = __float2bfloat16(u0), h1 = __float2bfloat16(u1);
        __nv_bfloat16 h2 = __float2bfloat16(v0), h3 = __float2bfloat16(v1);
        __nv_bfloat162 hh0 = {h0, h1}, hh1 = {h2, h3};
        __nv_bfloat162 ll0 = {__float2bfloat16(u0 - __bfloat162float(h0)),
                              __float2bfloat16(u1 - __bfloat162float(h1))};
        __nv_bfloat162 ll1 = {__float2bfloat16(v0 - __bfloat162float(h2)),
                              __float2bfloat16(v1 - __bfloat162float(h3))};
        *(__nv_bfloat162*)(oh + base0 + j * 8) = hh0;
        *(__nv_bfloat162*)(ol + base0 + j * 8) = ll0;
        *(__nv_bfloat162*)(oh + base1 + j * 8) = hh1;
        *(__nv_bfloat162*)(ol + base1 + j * 8) = ll1;
    }
}

// ---------------- Fourier branch (analytically reduced) + LayerNorm --------
__global__ __launch_bounds__(128)
void fourier_kernel(const float* __restrict__ x,
                    const float* __restrict__ fconv_w,
                    const float* __restrict__ fconv_b,
                    const float* __restrict__ freq_w,
                    const float* __restrict__ ln_g,
                    const float* __restrict__ ln_b,
                    float* __restrict__ outp) {
    const int row = blockIdx.x;
    const int tid = threadIdx.x;
    const int c = tid * 4;

    float4 xv = *(const float4*)(x + (size_t)row * CD + c);
    float4 fw = *(const float4*)(freq_w + c);
    float4 cw = *(const float4*)(fconv_w + c);
    float y[4];
    y[0] = xv.x * (fw.x + 0.1f * cw.x);
    y[1] = xv.y * (fw.y + 0.1f * cw.y);
    y[2] = xv.z * (fw.z + 0.1f * cw.z);
    y[3] = xv.w * (fw.w + 0.1f * cw.w);
    if ((row & (NPIX - 1)) == 0) {
        float4 cb = *(const float4*)(fconv_b + c);
        y[0] += 3.2f * cb.x;
        y[1] += 3.2f * cb.y;
        y[2] += 3.2f * cb.z;
        y[3] += 3.2f * cb.w;
    }
    float sum = y[0] + y[1] + y[2] + y[3];
    float sq = y[0] * y[0] + y[1] * y[1] + y[2] * y[2] + y[3] * y[3];
#pragma unroll
    for (int off = 16; off > 0; off >>= 1) {
        sum += __shfl_xor_sync(0xffffffffu, sum, off);
        sq += __shfl_xor_sync(0xffffffffu, sq, off);
    }
    __shared__ float ss[4], sx[4];
    if ((tid & 31) == 0) {
        ss[tid >> 5] = sum;
        sx[tid >> 5] = sq;
    }
    __syncthreads();
    sum = ss[0] + ss[1] + ss[2] + ss[3];
    sq = sx[0] + sx[1] + sx[2] + sx[3];
    float mu = sum * (1.f / 512.f);
    float var = sq * (1.f / 512.f) - mu * mu;
    float rstd = rsqrtf(var + 1e-5f);
    float4 g = *(const float4*)(ln_g + c);
    float4 bb = *(const float4*)(ln_b + c);
    float4 o;
    o.x = (y[0] - mu) * rstd * g.x + bb.x;
    o.y = (y[1] - mu) * rstd * g.y + bb.y;
    o.z = (y[2] - mu) * rstd * g.z + bb.z;
    o.w = (y[3] - mu) * rstd * g.w + bb.w;
    *(float4*)(outp + (size_t)row * CD + c) = o;
}

// ---------------- launch ----------------------------------------------------
extern "C" void kernel_launch(void* const* d_in, const int* in_sizes, int n_in,
                              void* d_out, int out_size) {
    const float* x       = (const float*)d_in[0];
    const float* qkv_w   = (const float*)d_in[1];
    const float* proj_w  = (const float*)d_in[2];
    const float* proj_b  = (const float*)d_in[3];
    const float* fconv_w = (const float*)d_in[4];
    const float* fconv_b = (const float*)d_in[5];
    const float* freq_w  = (const float*)d_in[6];
    const float* ln_g    = (const float*)d_in[7];
    const float* ln_b    = (const float*)d_in[8];
    const float* mix_w   = (const float*)d_in[9];
    float* out = (float*)d_out;

    __half* qkvh;
    float* four_p;
    __nv_bfloat16 *xh, *xl, *ah, *al, *wqh, *wql, *pwh, *pwl;
    cudaGetSymbolAddress((void**)&qkvh, g_qkvh);
    cudaGetSymbolAddress((void**)&four_p, g_four);
    cudaGetSymbolAddress((void**)&xh, g_xh);
    cudaGetSymbolAddress((void**)&xl, g_xl);
    cudaGetSymbolAddress((void**)&ah, g_ah);
    cudaGetSymbolAddress((void**)&al, g_al);
    cudaGetSymbolAddress((void**)&wqh, g_wqh);
    cudaGetSymbolAddress((void**)&wql, g_wql);
    cudaGetSymbolAddress((void**)&pwh, g_pwh);
    cudaGetSymbolAddress((void**)&pwl, g_pwl);

    const int GEMM_SMEM = 4 * 40960;   // 163840
    cudaFuncSetAttribute(gemm_mma<0>,
                         cudaFuncAttributeMaxDynamicSharedMemorySize, GEMM_SMEM);
    cudaFuncSetAttribute(gemm_mma<1>,
                         cudaFuncAttributeMaxDynamicSharedMemorySize, GEMM_SMEM);

    // 1) converts
    conv_hl<<<4096, 256>>>(x, xh, xl, BQ * NPIX * CD / 4);
    conv_hl<<<768, 256>>>(qkv_w, wqh, wql, 3 * CD * CD / 4);
    conv_hl<<<256, 256>>>(proj_w, pwh, pwl, CD * CD / 4);

    // 2) QKV GEMM (HMMA bf16 x3), fp16 output
    gemm_mma<0><<<dim3(12, 64), 256, GEMM_SMEM>>>(
        xh, xl, wqh, wql, qkvh, 1536, nullptr, nullptr, nullptr);

    // 3) Fourier branch
    fourier_kernel<<<BQ * NPIX, 128>>>(x, fconv_w, fconv_b, freq_w, ln_g,
                                       ln_b, four_p);

    // 4) flash attention (fp16 HMMA), writes bf16 hi/lo directly
    attn_mma<<<dim3(16, 64), 128>>>(qkvh, ah, al);

    // 5) proj GEMM + fused mix
    gemm_mma<1><<<dim3(4, 64), 256, GEMM_SMEM>>>(
        ah, al, pwh, pwl, out, 512, proj_b, four_p, mix_w);
}

// round 5
// speedup vs baseline: 6.0869x; 1.7470x over previous
#include <cuda_runtime.h>
#include <cuda_fp16.h>
#include <math.h>
#include <stdint.h>

#define BQ   8
#define NPIX 1024
#define CD   512
#define NH   8
#define HD   64

// ---------------- scratch (device globals; allocation-free rule) -----------
__device__ __half g_xf[BQ * NPIX * CD];                // x fp16
__device__ __half g_wq[3 * CD * CD];                   // qkv_w fp16
__device__ __half g_pw[CD * CD];                       // proj_w fp16
__device__ __half g_qkvh[BQ * NPIX * 3 * CD];          // qkv out fp16
__device__ __half g_ao[BQ * NPIX * CD];                // attn out fp16
__device__ float  g_four[BQ * NPIX * CD];              // fourier branch fp32

// ---------------- PTX helpers ----------------------------------------------
__device__ __forceinline__ uint32_t smem_u32(const void* p) {
    uint32_t a;
    asm("{ .reg .u64 t; cvta.to.shared.u64 t, %1; cvt.u32.u64 %0, t; }"
        : "=r"(a) : "l"(p));
    return a;
}
__device__ __forceinline__ void cp16(uint32_t dst, const void* src) {
    asm volatile("cp.async.cg.shared.global [%0], [%1], 16;"
                 :: "r"(dst), "l"(src) : "memory");
}
#define CP_COMMIT() asm volatile("cp.async.commit_group;" ::: "memory")
#define CP_WAIT0()  asm volatile("cp.async.wait_group 0;" ::: "memory")
#define CP_WAIT1()  asm volatile("cp.async.wait_group 1;" ::: "memory")
#define CP_WAIT2()  asm volatile("cp.async.wait_group 2;" ::: "memory")

__device__ __forceinline__ void ldsm4(uint32_t (&r)[4], uint32_t a) {
    asm volatile("ldmatrix.sync.aligned.m8n8.x4.shared.b16 {%0,%1,%2,%3}, [%4];"
                 : "=r"(r[0]), "=r"(r[1]), "=r"(r[2]), "=r"(r[3]) : "r"(a));
}
__device__ __forceinline__ void ldsm4t(uint32_t (&r)[4], uint32_t a) {
    asm volatile("ldmatrix.sync.aligned.m8n8.x4.trans.shared.b16 {%0,%1,%2,%3}, [%4];"
                 : "=r"(r[0]), "=r"(r[1]), "=r"(r[2]), "=r"(r[3]) : "r"(a));
}
__device__ __forceinline__ void mma_f16(float (&d)[4], const uint32_t (&a)[4],
                                        uint32_t b0, uint32_t b1) {
    asm volatile(
        "mma.sync.aligned.m16n8k16.row.col.f32.f16.f16.f32 "
        "{%0,%1,%2,%3}, {%4,%5,%6,%7}, {%8,%9}, {%0,%1,%2,%3};"
        : "+f"(d[0]), "+f"(d[1]), "+f"(d[2]), "+f"(d[3])
        : "r"(a[0]), "r"(a[1]), "r"(a[2]), "r"(a[3]), "r"(b0), "r"(b1));
}

// ---------------- fp32 -> fp16 elementwise ----------------------------------
__global__ __launch_bounds__(256)
void conv_f16(const float* __restrict__ src, __half* __restrict__ dst, int n4) {
    int i = blockIdx.x * 256 + threadIdx.x;
    if (i >= n4) return;
    float4 v = ((const float4*)src)[i];
    __half2 a = __float22half2_rn(make_float2(v.x, v.y));
    __half2 b = __float22half2_rn(make_float2(v.z, v.w));
    uint2 u;
    u.x = *(uint32_t*)&a;
    u.y = *(uint32_t*)&b;
    ((uint2*)dst)[i] = u;
}

// ---------------- fp16 HMMA GEMM: C[M,N] = A[M,512] @ B[N,512]^T ------------
// 128x128 tile, BK=32, 256 threads (8 warps, 2Mx4N, warp tile 64x32),
// 4-stage cp.async pipeline, 2 CTAs/SM. MODE 0: fp16 out. MODE 1: fp32+bias+mix.
template <int MODE>
__global__ __launch_bounds__(256, 2)
void gemm_f16(const __half* __restrict__ A, const __half* __restrict__ B,
              void* __restrict__ Cout, int N,
              const float* __restrict__ bias, const float* __restrict__ four,
              const float* __restrict__ mixw) {
    extern __shared__ __align__(16) char sm[];
    const uint32_t sbase = smem_u32(sm);
    const int tid = threadIdx.x, w = tid >> 5, lane = tid & 31;
    const int wm = w & 1, wn = w >> 1;          // 2 x 4 warps
    const int m0 = blockIdx.y * 128, n0 = blockIdx.x * 128;

    const int lrA = lane & 15, lcA = (lane >> 4) << 3;
    const int lrB = ((lane >> 4) & 1) * 8 + (lane & 7);
    const int lcB = ((lane >> 3) & 1) * 8;

    float acc[4][4][4];                          // [mt][j][frag]
#pragma unroll
    for (int mt = 0; mt < 4; mt++)
#pragma unroll
        for (int j = 0; j < 4; j++)
#pragma unroll
            for (int r = 0; r < 4; r++) acc[mt][j][r] = 0.f;

    // stage: A @0, B @10240 ; stride 20480, 4 stages (80KB)
    auto load_stage = [&](int kt) {
        uint32_t sb = sbase + (kt & 3) * 20480;
#pragma unroll
        for (int i = 0; i < 4; i++) {
            int idx = tid + i * 256;             // 0..1023
            int mat = idx >> 9, rem = idx & 511;
            int r = rem >> 2, c = rem & 3;
            const __half* g = (mat == 0) ? A : B;
            int rowbase = (mat == 0) ? m0 : n0;
            const void* src = g + (size_t)(rowbase + r) * 512 + kt * 32 + c * 8;
            cp16(sb + mat * 10240 + (r * 40 + c * 8) * 2, src);
        }
    };

    load_stage(0);
    CP_COMMIT();
    load_stage(1);
    CP_COMMIT();

    for (int kt = 0; kt < 16; kt++) {
        if (kt < 14) {
            load_stage(kt + 2);
            CP_COMMIT();
            CP_WAIT2();
        } else {
            CP_WAIT0();
        }
        __syncthreads();

        uint32_t sb = sbase + (kt & 3) * 20480;
#pragma unroll
        for (int ks = 0; ks < 2; ks++) {
            uint32_t af[4][4];
#pragma unroll
            for (int mt = 0; mt < 4; mt++) {
                uint32_t off =
                    ((wm * 64 + mt * 16 + lrA) * 40 + ks * 16 + lcA) * 2;
                ldsm4(af[mt], sb + off);
            }
            uint32_t bf[2][4];
#pragma unroll
            for (int g = 0; g < 2; g++) {
                uint32_t off =
                    ((wn * 32 + g * 16 + lrB) * 40 + ks * 16 + lcB) * 2;
                ldsm4(bf[g], sb + 10240 + off);
            }
#pragma unroll
            for (int mt = 0; mt < 4; mt++)
#pragma unroll
                for (int g = 0; g < 2; g++) {
                    mma_f16(acc[mt][2 * g], af[mt], bf[g][0], bf[g][1]);
                    mma_f16(acc[mt][2 * g + 1], af[mt], bf[g][2], bf[g][3]);
                }
        }
        __syncthreads();
    }

    float w0 = 1.f, w1 = 0.f;
    if (MODE == 1) {
        float a = mixw[0], b = mixw[1];
        float mx = fmaxf(a, b);
        float e0 = __expf(a - mx), e1 = __expf(b - mx);
        float inv = 1.f / (e0 + e1);
        w0 = e0 * inv;
        w1 = e1 * inv;
    }
#pragma unroll
    for (int mt = 0; mt < 4; mt++) {
        int r0 = m0 + wm * 64 + mt * 16 + (lane >> 2);
        int r1 = r0 + 8;
#pragma unroll
        for (int j = 0; j < 4; j++) {
            int col = n0 + wn * 32 + j * 8 + (lane & 3) * 2;
            if (MODE == 0) {
                __half* O = (__half*)Cout;
                *(__half2*)(O + (size_t)r0 * N + col) =
                    __float22half2_rn(make_float2(acc[mt][j][0], acc[mt][j][1]));
                *(__half2*)(O + (size_t)r1 * N + col) =
                    __float22half2_rn(make_float2(acc[mt][j][2], acc[mt][j][3]));
            } else {
                float* O = (float*)Cout;
                float b0 = bias[col], b1 = bias[col + 1];
                const float* f0 = four + (size_t)r0 * N + col;
                const float* f1 = four + (size_t)r1 * N + col;
                float2 o0, o1;
                o0.x = w0 * (acc[mt][j][0] + b0) + w1 * f0[0];
                o0.y = w0 * (acc[mt][j][1] + b1) + w1 * f0[1];
                o1.x = w0 * (acc[mt][j][2] + b0) + w1 * f1[0];
                o1.y = w0 * (acc[mt][j][3] + b1) + w1 * f1[1];
                *(float2*)(O + (size_t)r0 * N + col) = o0;
                *(float2*)(O + (size_t)r1 * N + col) = o1;
            }
        }
    }
}

// ---------------- FA2-style fp16 HMMA flash attention -----------------------
__global__ __launch_bounds__(128)
void attn_mma(const __half* __restrict__ qkvh, __half* __restrict__ outp) {
    __shared__ __align__(16) __half sQ[64 * 72];
    __shared__ __align__(16) __half sKV[2][2][64 * 72];

    const int tid = threadIdx.x, w = tid >> 5, lane = tid & 31;
    const int qt = blockIdx.x, bh = blockIdx.y;
    const int b = bh >> 3, h = bh & 7;
    const __half* base = qkvh + (size_t)b * NPIX * 1536 + h * 64;

    const uint32_t sQa = smem_u32(sQ);
    const uint32_t sKVa = smem_u32(sKV);

    const int lrA = lane & 15, lcA = (lane >> 4) << 3;
    const int lrB = ((lane >> 4) & 1) * 8 + (lane & 7);
    const int lcB = ((lane >> 3) & 1) * 8;
    const int lrV = ((lane >> 3) & 1) * 8 + (lane & 7);
    const int lcV = ((lane >> 4) & 1) * 8;

#pragma unroll
    for (int i = 0; i < 4; i++) {
        int idx = tid + i * 128;
        int r = idx >> 3, c = idx & 7;
        cp16(sQa + (r * 72 + c * 8) * 2,
             base + (size_t)(qt * 64 + r) * 1536 + c * 8);
    }
#pragma unroll
    for (int i = 0; i < 8; i++) {
        int idx = tid + i * 128;
        int m = idx >> 9, rem = idx & 511;
        int r = rem >> 3, c = rem & 7;
        cp16(sKVa + (m * 4608 + r * 72 + c * 8) * 2,
             base + (size_t)r * 1536 + 512 + m * 512 + c * 8);
    }
    CP_COMMIT();

    float oacc[8][4];
#pragma unroll
    for (int j = 0; j < 8; j++)
#pragma unroll
        for (int r = 0; r < 4; r++) oacc[j][r] = 0.f;
    float m0 = -1e30f, m1 = -1e30f, l0 = 0.f, l1 = 0.f;
    uint32_t qf[4][4];
    const float SC = 0.125f * 1.44269504f;

    for (int kt = 0; kt < 16; kt++) {
        if (kt < 15) {
            int nb = (kt + 1) & 1;
#pragma unroll
            for (int i = 0; i < 8; i++) {
                int idx = tid + i * 128;
                int m = idx >> 9, rem = idx & 511;
                int r = rem >> 3, c = rem & 7;
                cp16(sKVa + ((nb * 2 + m) * 4608 + r * 72 + c * 8) * 2,
                     base + (size_t)((kt + 1) * 64 + r) * 1536 + 512 + m * 512 +
                         c * 8);
            }
            CP_COMMIT();
            CP_WAIT1();
        } else {
            CP_WAIT0();
        }
        __syncthreads();

        if (kt == 0) {
#pragma unroll
            for (int ds = 0; ds < 4; ds++)
                ldsm4(qf[ds], sQa + ((w * 16 + lrA) * 72 + ds * 16 + lcA) * 2);
        }

        const uint32_t sK = sKVa + ((kt & 1) * 2 + 0) * 4608 * 2;
        const uint32_t sV = sKVa + ((kt & 1) * 2 + 1) * 4608 * 2;

        float sacc[8][4];
#pragma unroll
        for (int j = 0; j < 8; j++)
#pragma unroll
            for (int r = 0; r < 4; r++) sacc[j][r] = 0.f;
#pragma unroll
        for (int ds = 0; ds < 4; ds++) {
#pragma unroll
            for (int g = 0; g < 4; g++) {
                uint32_t kb[4];
                ldsm4(kb, sK + ((g * 16 + lrB) * 72 + ds * 16 + lcB) * 2);
                mma_f16(sacc[2 * g], qf[ds], kb[0], kb[1]);
                mma_f16(sacc[2 * g + 1], qf[ds], kb[2], kb[3]);
            }
        }

        float rm0 = -1e30f, rm1 = -1e30f;
#pragma unroll
        for (int j = 0; j < 8; j++) {
#pragma unroll
            for (int r = 0; r < 4; r++) sacc[j][r] *= SC;
            rm0 = fmaxf(rm0, fmaxf(sacc[j][0], sacc[j][1]));
            rm1 = fmaxf(rm1, fmaxf(sacc[j][2], sacc[j][3]));
        }
        rm0 = fmaxf(rm0, __shfl_xor_sync(0xffffffffu, rm0, 1));
        rm0 = fmaxf(rm0, __shfl_xor_sync(0xffffffffu, rm0, 2));
        rm1 = fmaxf(rm1, __shfl_xor_sync(0xffffffffu, rm1, 1));
        rm1 = fmaxf(rm1, __shfl_xor_sync(0xffffffffu, rm1, 2));
        float mn0 = fmaxf(m0, rm0), mn1 = fmaxf(m1, rm1);
        float a0 = exp2f(m0 - mn0), a1 = exp2f(m1 - mn1);
        m0 = mn0;
        m1 = mn1;

        float rs0 = 0.f, rs1 = 0.f;
        uint32_t pf[4][4];
#pragma unroll
        for (int j = 0; j < 8; j++) {
            float p0 = exp2f(sacc[j][0] - mn0);
            float p1 = exp2f(sacc[j][1] - mn0);
            float p2 = exp2f(sacc[j][2] - mn1);
            float p3 = exp2f(sacc[j][3] - mn1);
            rs0 += p0 + p1;
            rs1 += p2 + p3;
            int ks = j >> 1, t = (j & 1) * 2;
            __half2 h01 = __float22half2_rn(make_float2(p0, p1));
            __half2 h23 = __float22half2_rn(make_float2(p2, p3));
            pf[ks][t] = *(uint32_t*)&h01;
            pf[ks][t + 1] = *(uint32_t*)&h23;
        }
        rs0 += __shfl_xor_sync(0xffffffffu, rs0, 1);
        rs0 += __shfl_xor_sync(0xffffffffu, rs0, 2);
        rs1 += __shfl_xor_sync(0xffffffffu, rs1, 1);
        rs1 += __shfl_xor_sync(0xffffffffu, rs1, 2);
        l0 = l0 * a0 + rs0;
        l1 = l1 * a1 + rs1;
#pragma unroll
        for (int j = 0; j < 8; j++) {
            oacc[j][0] *= a0;
            oacc[j][1] *= a0;
            oacc[j][2] *= a1;
            oacc[j][3] *= a1;
        }

#pragma unroll
        for (int ks = 0; ks < 4; ks++) {
#pragma unroll
            for (int gd = 0; gd < 4; gd++) {
                uint32_t vb[4];
                ldsm4t(vb, sV + ((ks * 16 + lrV) * 72 + gd * 16 + lcV) * 2);
                mma_f16(oacc[2 * gd], pf[ks], vb[0], vb[1]);
                mma_f16(oacc[2 * gd + 1], pf[ks], vb[2], vb[3]);
            }
        }
        __syncthreads();
    }

    float inv0 = 1.f / l0, inv1 = 1.f / l1;
    int r0 = qt * 64 + w * 16 + (lane >> 2);
    int r1 = r0 + 8;
    __half* o0 = outp + (size_t)(b * NPIX + r0) * CD + h * 64 + (lane & 3) * 2;
    __half* o1 = outp + (size_t)(b * NPIX + r1) * CD + h * 64 + (lane & 3) * 2;
#pragma unroll
    for (int j = 0; j < 8; j++) {
        *(__half2*)(o0 + j * 8) = __float22half2_rn(
            make_float2(oacc[j][0] * inv0, oacc[j][1] * inv0));
        *(__half2*)(o1 + j * 8) = __float22half2_rn(
            make_float2(oacc[j][2] * inv1, oacc[j][3] * inv1));
    }
}

// ---------------- Fourier branch (analytically reduced) + LayerNorm --------
__global__ __launch_bounds__(128)
void fourier_kernel(const float* __restrict__ x,
                    const float* __restrict__ fconv_w,
                    const float* __restrict__ fconv_b,
                    const float* __restrict__ freq_w,
                    const float* __restrict__ ln_g,
                    const float* __restrict__ ln_b,
                    float* __restrict__ outp) {
    const int row = blockIdx.x;
    const int tid = threadIdx.x;
    const int c = tid * 4;

    float4 xv = *(const float4*)(x + (size_t)row * CD + c);
    float4 fw = *(const float4*)(freq_w + c);
    float4 cw = *(const float4*)(fconv_w + c);
    float y[4];
    y[0] = xv.x * (fw.x + 0.1f * cw.x);
    y[1] = xv.y * (fw.y + 0.1f * cw.y);
    y[2] = xv.z * (fw.z + 0.1f * cw.z);
    y[3] = xv.w * (fw.w + 0.1f * cw.w);
    if ((row & (NPIX - 1)) == 0) {
        float4 cb = *(const float4*)(fconv_b + c);
        y[0] += 3.2f * cb.x;
        y[1] += 3.2f * cb.y;
        y[2] += 3.2f * cb.z;
        y[3] += 3.2f * cb.w;
    }
    float sum = y[0] + y[1] + y[2] + y[3];
    float sq = y[0] * y[0] + y[1] * y[1] + y[2] * y[2] + y[3] * y[3];
#pragma unroll
    for (int off = 16; off > 0; off >>= 1) {
        sum += __shfl_xor_sync(0xffffffffu, sum, off);
        sq += __shfl_xor_sync(0xffffffffu, sq, off);
    }
    __shared__ float ss[4], sx[4];
    if ((tid & 31) == 0) {
        ss[tid >> 5] = sum;
        sx[tid >> 5] = sq;
    }
    __syncthreads();
    sum = ss[0] + ss[1] + ss[2] + ss[3];
    sq = sx[0] + sx[1] + sx[2] + sx[3];
    float mu = sum * (1.f / 512.f);
    float var = sq * (1.f / 512.f) - mu * mu;
    float rstd = rsqrtf(var + 1e-5f);
    float4 g = *(const float4*)(ln_g + c);
    float4 bb = *(const float4*)(ln_b + c);
    float4 o;
    o.x = (y[0] - mu) * rstd * g.x + bb.x;
    o.y = (y[1] - mu) * rstd * g.y + bb.y;
    o.z = (y[2] - mu) * rstd * g.z + bb.z;
    o.w = (y[3] - mu) * rstd * g.w + bb.w;
    *(float4*)(outp + (size_t)row * CD + c) = o;
}

// ---------------- launch ----------------------------------------------------
extern "C" void kernel_launch(void* const* d_in, const int* in_sizes, int n_in,
                              void* d_out, int out_size) {
    const float* x       = (const float*)d_in[0];
    const float* qkv_w   = (const float*)d_in[1];
    const float* proj_w  = (const float*)d_in[2];
    const float* proj_b  = (const float*)d_in[3];
    const float* fconv_w = (const float*)d_in[4];
    const float* fconv_b = (const float*)d_in[5];
    const float* freq_w  = (const float*)d_in[6];
    const float* ln_g    = (const float*)d_in[7];
    const float* ln_b    = (const float*)d_in[8];
    const float* mix_w   = (const float*)d_in[9];
    float* out = (float*)d_out;

    __half *xf, *wq, *pw, *qkvh, *ao;
    float* four_p;
    cudaGetSymbolAddress((void**)&xf, g_xf);
    cudaGetSymbolAddress((void**)&wq, g_wq);
    cudaGetSymbolAddress((void**)&pw, g_pw);
    cudaGetSymbolAddress((void**)&qkvh, g_qkvh);
    cudaGetSymbolAddress((void**)&ao, g_ao);
    cudaGetSymbolAddress((void**)&four_p, g_four);

    const int GEMM_SMEM = 4 * 20480;   // 81920
    cudaFuncSetAttribute(gemm_f16<0>,
                         cudaFuncAttributeMaxDynamicSharedMemorySize, GEMM_SMEM);
    cudaFuncSetAttribute(gemm_f16<1>,
                         cudaFuncAttributeMaxDynamicSharedMemorySize, GEMM_SMEM);

    // 1) converts (fp32 -> fp16)
    conv_f16<<<4096, 256>>>(x, xf, BQ * NPIX * CD / 4);
    conv_f16<<<768, 256>>>(qkv_w, wq, 3 * CD * CD / 4);
    conv_f16<<<256, 256>>>(proj_w, pw, CD * CD / 4);

    // 2) QKV GEMM (fp16 HMMA), fp16 output
    gemm_f16<0><<<dim3(12, 64), 256, GEMM_SMEM>>>(
        xf, wq, qkvh, 1536, nullptr, nullptr, nullptr);

    // 3) Fourier branch
    fourier_kernel<<<BQ * NPIX, 128>>>(x, fconv_w, fconv_b, freq_w, ln_g,
                                       ln_b, four_p);

    // 4) flash attention (fp16 HMMA), fp16 output
    attn_mma<<<dim3(16, 64), 128>>>(qkvh, ao);

    // 5) proj GEMM + fused mix
    gemm_f16<1><<<dim3(4, 64), 256, GEMM_SMEM>>>(
        ao, pw, out, 512, proj_b, four_p, mix_w);
}